// round 1
// baseline (speedup 1.0000x reference)
#include <cuda_runtime.h>
#include <math.h>

// ======================= device scratch (no allocations allowed) ==========
#define BUF_ELEMS (4u*64u*256u*256u)   /* 16,777,216 floats = 64 MB */
__device__ float g_bufA[BUF_ELEMS];
__device__ float g_bufB[BUF_ELEMS];
__device__ float g_bufC[BUF_ELEMS];
__device__ float g_wT[3503808];        /* all transposed weights */
__device__ float g_cm[1024], g_cs[1024], g_sm[1024], g_ssd[1024];
__device__ float g_a[1024],  g_bsh[1024];
__device__ float g_blurk[12*81];

// ======================= weight transpose: [co][ci][9] -> [(ci*9+t)][co] ==
__global__ void transpose_w(const float* __restrict__ src, float* __restrict__ dst,
                            int Cin, int Cout)
{
    int idx = blockIdx.x * blockDim.x + threadIdx.x;
    int total = Cin * Cout * 9;
    if (idx >= total) return;
    int co = idx % Cout;
    int t  = (idx / Cout) % 9;
    int ci = idx / (Cout * 9);
    dst[idx] = src[((size_t)co * Cin + ci) * 9 + t];
}

// ======================= per-sample masked gaussian kernels ===============
__global__ void build_blur(const float* __restrict__ alphas)
{
    int i = threadIdx.x;        // 0..11 : b*3 + col
    if (i >= 12) return;
    float alpha = alphas[i];
    float k = floorf(floorf(alpha * 8.0f) * 0.5f) * 2.0f + 1.0f;
    float r = (k - 1.0f) * 0.5f;
    float vals[81];
    float sum = 0.0f;
    for (int y = 0; y < 9; y++)
        for (int x = 0; x < 9; x++) {
            float cy = (float)(y - 4), cx = (float)(x - 4);
            float g = expf(-(cy*cy + cx*cx) / 512.0f);
            float v = (fabsf(cy) <= r && fabsf(cx) <= r) ? g : 0.0f;
            vals[y*9 + x] = v;
            sum += v;
        }
    float inv = 1.0f / sum;
    for (int j = 0; j < 81; j++) g_blurk[i*81 + j] = vals[j] * inv;
}

// ======================= channel stats (mean + unbiased std) ==============
// which == 0 -> write g_cm/g_cs ; which == 1 -> write g_sm/g_ssd
__global__ void stats_kernel(const float* __restrict__ x, int HW, int which)
{
    int bc = blockIdx.x;
    const float* p = x + (size_t)bc * HW;
    float s = 0.f, s2 = 0.f;
    for (int i = threadIdx.x; i < HW; i += blockDim.x) {
        float v = p[i];
        s += v;
        s2 = fmaf(v, v, s2);
    }
#pragma unroll
    for (int o = 16; o > 0; o >>= 1) {
        s  += __shfl_down_sync(0xffffffffu, s,  o);
        s2 += __shfl_down_sync(0xffffffffu, s2, o);
    }
    __shared__ float rs[8], rs2[8];
    int w = threadIdx.x >> 5, l = threadIdx.x & 31;
    if (l == 0) { rs[w] = s; rs2[w] = s2; }
    __syncthreads();
    if (threadIdx.x == 0) {
        float S = 0.f, S2 = 0.f;
        for (int i = 0; i < 8; i++) { S += rs[i]; S2 += rs2[i]; }
        float n = (float)HW;
        float mean = S / n;
        float var = (S2 - S * S / n) / (n - 1.0f);
        if (var < 0.f) var = 0.f;
        float sd = sqrtf(var);
        if (which == 0) { g_cm[bc] = mean; g_cs[bc]  = sd; }
        else            { g_sm[bc] = mean; g_ssd[bc] = sd; }
    }
}

// scale = ss/(cs+eps), shift = sm - cm*scale
__global__ void combine_kernel(int n)
{
    int i = blockIdx.x * blockDim.x + threadIdx.x;
    if (i >= n) return;
    float a = g_ssd[i] / (g_cs[i] + 1e-5f);
    g_a[i]   = a;
    g_bsh[i] = g_sm[i] - g_cm[i] * a;
}

// in-place AdaIN apply; sh = log2(H*W)
__global__ void wct_apply_kernel(float* __restrict__ x, int sh)
{
    int idx = blockIdx.x * blockDim.x + threadIdx.x;
    int bc = idx >> sh;
    x[idx] = fmaf(x[idx], g_a[bc], g_bsh[bc]);
}

// hh = x - up2(avgpool2(x));  W = 1<<wsh, H = 1<<hsh, square images here
__global__ void hh_kernel(const float* __restrict__ x, float* __restrict__ o,
                          int wsh, int hsh)
{
    int idx = blockIdx.x * blockDim.x + threadIdx.x;
    int W = 1 << wsh;
    int xc = idx & (W - 1);
    int y  = (idx >> wsh) & ((1 << hsh) - 1);
    size_t chbase = ((size_t)(idx >> (wsh + hsh))) << (wsh + hsh);
    int y0 = y & ~1, x0 = xc & ~1;
    const float* ch = x + chbase;
    size_t b0 = (size_t)y0 * W + x0;
    float avg = 0.25f * (ch[b0] + ch[b0 + 1] + ch[b0 + W] + ch[b0 + W + 1]);
    o[idx] = x[idx] - avg;
}

// out = up2(small) + g_a[bc] * blur9x9(hh)   (replicate pad 4)
#define BT 16
__global__ void blur_add_kernel(const float* __restrict__ hh,
                                const float* __restrict__ small,
                                float* __restrict__ out,
                                int C, int H, int W, int lvl)
{
    int bc = blockIdx.z;
    int b  = bc / C;
    int ty0 = blockIdx.y * BT, tx0 = blockIdx.x * BT;
    __shared__ float tile[BT + 8][BT + 9];
    __shared__ float ker[81];
    int tid = threadIdx.x;
    if (tid < 81) ker[tid] = g_blurk[(b * 3 + lvl) * 81 + tid];
    const float* src = hh + (size_t)bc * H * W;
    for (int i = tid; i < (BT + 8) * (BT + 8); i += 256) {
        int r = i / (BT + 8), c = i % (BT + 8);
        int gy = ty0 - 4 + r; gy = gy < 0 ? 0 : (gy >= H ? H - 1 : gy);
        int gx = tx0 - 4 + c; gx = gx < 0 ? 0 : (gx >= W ? W - 1 : gx);
        tile[r][c] = src[(size_t)gy * W + gx];
    }
    __syncthreads();
    int ly = tid >> 4, lx = tid & 15;
    float s = 0.f;
#pragma unroll
    for (int dy = 0; dy < 9; dy++)
#pragma unroll
        for (int dx = 0; dx < 9; dx++)
            s = fmaf(ker[dy * 9 + dx], tile[ly + dy][lx + dx], s);
    int y = ty0 + ly, x = tx0 + lx;
    int W2 = W >> 1;
    size_t hw2 = (size_t)(H >> 1) * W2;
    float up = small[(size_t)bc * hw2 + (size_t)(y >> 1) * W2 + (x >> 1)];
    out[(size_t)bc * H * W + (size_t)y * W + x] = up + g_a[bc] * s;
}

// ======================= main conv3x3 (reflect pad 1) =====================
// block: 8x8 spatial tile x 64 output channels; thread: 4 px x 4 co.
#define TILE 8
#define COB  64
#define CCH  8
__global__ __launch_bounds__(256)
void conv3x3_kernel(const float* __restrict__ in, const float* __restrict__ wT,
                    const float* __restrict__ bias, float* __restrict__ out,
                    int Cin, int Cout, int H, int W, int doRelu)
{
    const int nCoG = Cout / COB;
    const int b       = blockIdx.z / nCoG;
    const int co_base = (blockIdx.z % nCoG) * COB;
    const int ty0 = blockIdx.y * TILE;
    const int tx0 = blockIdx.x * TILE;

    const int tid  = threadIdx.x;
    const int px_t = tid & 15;
    const int co_t = tid >> 4;

    __shared__ float sIn[CCH][10][12];
    __shared__ __align__(16) float sW[CCH][9][COB];

    float acc[4][4];
#pragma unroll
    for (int i = 0; i < 4; i++)
#pragma unroll
        for (int j = 0; j < 4; j++) acc[i][j] = 0.f;

    int py[4], pxl[4];
#pragma unroll
    for (int i = 0; i < 4; i++) {
        int p = px_t + 16 * i;
        py[i] = p >> 3; pxl[i] = p & 7;
    }

    const size_t chsz = (size_t)H * W;
    const float* inB = in + (size_t)b * Cin * chsz;

    for (int c0 = 0; c0 < Cin; c0 += CCH) {
        // input tiles (reflect pad 1)
        for (int idx = tid; idx < CCH * 100; idx += 256) {
            int ci = idx / 100; int rem = idx - ci * 100;
            int r = rem / 10, c = rem - r * 10;
            int gy = ty0 - 1 + r;
            int gx = tx0 - 1 + c;
            gy = gy < 0 ? -gy : (gy >= H ? 2 * H - 2 - gy : gy);
            gx = gx < 0 ? -gx : (gx >= W ? 2 * W - 2 - gx : gx);
            sIn[ci][r][c] = inB[(size_t)(c0 + ci) * chsz + (size_t)gy * W + gx];
        }
        // weight tiles: wT layout [(ci*9+t)*Cout + co] -> coalesced over co
        for (int idx = tid; idx < CCH * 9 * COB; idx += 256) {
            int ci = idx / (9 * COB); int rem = idx - ci * (9 * COB);
            int t = rem / COB; int co = rem - t * COB;
            sW[ci][t][co] = wT[((size_t)(c0 + ci) * 9 + t) * Cout + co_base + co];
        }
        __syncthreads();
        for (int ci = 0; ci < CCH; ci++) {
#pragma unroll
            for (int t = 0; t < 9; t++) {
                const int dy = t / 3, dx = t - 3 * (t / 3);
                float4 wv = *reinterpret_cast<const float4*>(&sW[ci][t][co_t << 2]);
                float r0 = sIn[ci][py[0] + dy][pxl[0] + dx];
                float r1 = sIn[ci][py[1] + dy][pxl[1] + dx];
                float r2 = sIn[ci][py[2] + dy][pxl[2] + dx];
                float r3 = sIn[ci][py[3] + dy][pxl[3] + dx];
                acc[0][0] = fmaf(r0, wv.x, acc[0][0]);
                acc[0][1] = fmaf(r0, wv.y, acc[0][1]);
                acc[0][2] = fmaf(r0, wv.z, acc[0][2]);
                acc[0][3] = fmaf(r0, wv.w, acc[0][3]);
                acc[1][0] = fmaf(r1, wv.x, acc[1][0]);
                acc[1][1] = fmaf(r1, wv.y, acc[1][1]);
                acc[1][2] = fmaf(r1, wv.z, acc[1][2]);
                acc[1][3] = fmaf(r1, wv.w, acc[1][3]);
                acc[2][0] = fmaf(r2, wv.x, acc[2][0]);
                acc[2][1] = fmaf(r2, wv.y, acc[2][1]);
                acc[2][2] = fmaf(r2, wv.z, acc[2][2]);
                acc[2][3] = fmaf(r2, wv.w, acc[2][3]);
                acc[3][0] = fmaf(r3, wv.x, acc[3][0]);
                acc[3][1] = fmaf(r3, wv.y, acc[3][1]);
                acc[3][2] = fmaf(r3, wv.z, acc[3][2]);
                acc[3][3] = fmaf(r3, wv.w, acc[3][3]);
            }
        }
        __syncthreads();
    }
    float* outB = out + ((size_t)b * Cout + co_base) * chsz;
#pragma unroll
    for (int j = 0; j < 4; j++) {
        int co = co_t * 4 + j;
        float bv = bias[co_base + co];
#pragma unroll
        for (int i = 0; i < 4; i++) {
            float v = acc[i][j] + bv;
            if (doRelu) v = fmaxf(v, 0.f);
            outB[(size_t)co * chsz + (size_t)(ty0 + py[i]) * W + (tx0 + pxl[i])] = v;
        }
    }
}

// ======================= final conv (Cin=64, Cout=3, no relu) =============
__global__ __launch_bounds__(256)
void conv11_kernel(const float* __restrict__ in, const float* __restrict__ wT,
                   const float* __restrict__ bias, float* __restrict__ out,
                   int H, int W)
{
    int b = blockIdx.z;
    int ty0 = blockIdx.y * 16, tx0 = blockIdx.x * 16;
    __shared__ float sIn[8][18][18];
    __shared__ float sW[64 * 9 * 3];
    int tid = threadIdx.x;
    for (int i = tid; i < 64 * 9 * 3; i += 256) sW[i] = wT[i];
    float a0 = 0.f, a1 = 0.f, a2 = 0.f;
    int ly = tid >> 4, lx = tid & 15;
    const size_t chsz = (size_t)H * W;
    const float* inB = in + (size_t)b * 64 * chsz;
    for (int c0 = 0; c0 < 64; c0 += 8) {
        __syncthreads();
        for (int i = tid; i < 8 * 324; i += 256) {
            int ci = i / 324; int rem = i - ci * 324;
            int r = rem / 18, c = rem - r * 18;
            int gy = ty0 - 1 + r; gy = gy < 0 ? -gy : (gy >= H ? 2 * H - 2 - gy : gy);
            int gx = tx0 - 1 + c; gx = gx < 0 ? -gx : (gx >= W ? 2 * W - 2 - gx : gx);
            sIn[ci][r][c] = inB[(size_t)(c0 + ci) * chsz + (size_t)gy * W + gx];
        }
        __syncthreads();
        for (int ci = 0; ci < 8; ci++) {
#pragma unroll
            for (int t = 0; t < 9; t++) {
                float v = sIn[ci][ly + t / 3][lx + t % 3];
                int wb = ((c0 + ci) * 9 + t) * 3;
                a0 = fmaf(v, sW[wb + 0], a0);
                a1 = fmaf(v, sW[wb + 1], a1);
                a2 = fmaf(v, sW[wb + 2], a2);
            }
        }
    }
    int y = ty0 + ly, x = tx0 + lx;
    size_t off = (size_t)y * W + x;
    out[((size_t)b * 3 + 0) * chsz + off] = a0 + bias[0];
    out[((size_t)b * 3 + 1) * chsz + off] = a1 + bias[1];
    out[((size_t)b * 3 + 2) * chsz + off] = a2 + bias[2];
}

// ======================= host launcher ====================================
extern "C" void kernel_launch(void* const* d_in, const int* in_sizes, int n_in,
                              void* d_out, int out_size)
{
    const float* x   = (const float*)d_in[0];
    const float* c34 = (const float*)d_in[1];
    const float* c22 = (const float*)d_in[2];
    const float* c12 = (const float*)d_in[3];
    const float* s34 = (const float*)d_in[4];
    const float* s31 = (const float*)d_in[5];
    const float* s22 = (const float*)d_in[6];
    const float* s21 = (const float*)d_in[7];
    const float* s12 = (const float*)d_in[8];
    const float* s11 = (const float*)d_in[9];
    const float* alphas = (const float*)d_in[10];
    const float* wsrc[9] = { (const float*)d_in[11], (const float*)d_in[13],
                             (const float*)d_in[15], (const float*)d_in[17],
                             (const float*)d_in[19], (const float*)d_in[21],
                             (const float*)d_in[23], (const float*)d_in[25],
                             (const float*)d_in[27] };
    const float* bsrc[9] = { (const float*)d_in[12], (const float*)d_in[14],
                             (const float*)d_in[16], (const float*)d_in[18],
                             (const float*)d_in[20], (const float*)d_in[22],
                             (const float*)d_in[24], (const float*)d_in[26],
                             (const float*)d_in[28] };
    float* outp = (float*)d_out;

    float *pA, *pB, *pC, *wT;
    cudaGetSymbolAddress((void**)&pA, g_bufA);
    cudaGetSymbolAddress((void**)&pB, g_bufB);
    cudaGetSymbolAddress((void**)&pC, g_bufC);
    cudaGetSymbolAddress((void**)&wT, g_wT);

    // weight transposes
    const int cins[9]  = {512,256,256,256,256,128,128,64,64};
    const int couts[9] = {256,256,256,256,128,128, 64,64, 3};
    size_t offs[9]; size_t off = 0;
    for (int l = 0; l < 9; l++) { offs[l] = off; off += (size_t)cins[l]*couts[l]*9; }
    for (int l = 0; l < 9; l++) {
        int total = cins[l]*couts[l]*9;
        transpose_w<<<(total + 255)/256, 256>>>(wsrc[l], wT + offs[l], cins[l], couts[l]);
    }
    build_blur<<<1, 32>>>(alphas);

    // ---- level 4 -> 3 ----
    conv3x3_kernel<<<dim3(4,4,16), 256>>>(x, wT+offs[0], bsrc[0], pA, 512,256,32,32, 1);
    stats_kernel<<<1024, 256>>>(c34, 64*64, 0);
    stats_kernel<<<1024, 256>>>(s34, 64*64, 1);
    combine_kernel<<<4, 256>>>(1024);
    hh_kernel<<<(4*256*64*64)/256, 256>>>(c34, pC, 6, 6);
    blur_add_kernel<<<dim3(4,4,1024), 256>>>(pC, pA, pB, 256, 64, 64, 2);
    conv3x3_kernel<<<dim3(8,8,16), 256>>>(pB, wT+offs[1], bsrc[1], pA, 256,256,64,64, 1);
    conv3x3_kernel<<<dim3(8,8,16), 256>>>(pA, wT+offs[2], bsrc[2], pB, 256,256,64,64, 1);
    conv3x3_kernel<<<dim3(8,8,16), 256>>>(pB, wT+offs[3], bsrc[3], pA, 256,256,64,64, 1);
    stats_kernel<<<1024, 256>>>(pA,  64*64, 0);
    stats_kernel<<<1024, 256>>>(s31, 64*64, 1);
    combine_kernel<<<4, 256>>>(1024);
    wct_apply_kernel<<<(4*256*64*64)/256, 256>>>(pA, 12);
    conv3x3_kernel<<<dim3(8,8,8), 256>>>(pA, wT+offs[4], bsrc[4], pB, 256,128,64,64, 1);

    // ---- level 3 -> 2 ----
    stats_kernel<<<512, 256>>>(c22, 128*128, 0);
    stats_kernel<<<512, 256>>>(s22, 128*128, 1);
    combine_kernel<<<2, 256>>>(512);
    hh_kernel<<<(4*128*128*128)/256, 256>>>(c22, pC, 7, 7);
    blur_add_kernel<<<dim3(8,8,512), 256>>>(pC, pB, pA, 128, 128, 128, 1);
    conv3x3_kernel<<<dim3(16,16,8), 256>>>(pA, wT+offs[5], bsrc[5], pB, 128,128,128,128, 1);
    stats_kernel<<<512, 256>>>(pB,  128*128, 0);
    stats_kernel<<<512, 256>>>(s21, 128*128, 1);
    combine_kernel<<<2, 256>>>(512);
    wct_apply_kernel<<<(4*128*128*128)/256, 256>>>(pB, 14);
    conv3x3_kernel<<<dim3(16,16,4), 256>>>(pB, wT+offs[6], bsrc[6], pA, 128,64,128,128, 1);

    // ---- level 2 -> 1 ----
    stats_kernel<<<256, 256>>>(c12, 256*256, 0);
    stats_kernel<<<256, 256>>>(s12, 256*256, 1);
    combine_kernel<<<1, 256>>>(256);
    hh_kernel<<<(4*64*256*256)/256, 256>>>(c12, pC, 8, 8);
    blur_add_kernel<<<dim3(16,16,256), 256>>>(pC, pA, pB, 64, 256, 256, 0);
    conv3x3_kernel<<<dim3(32,32,4), 256>>>(pB, wT+offs[7], bsrc[7], pA, 64,64,256,256, 1);
    stats_kernel<<<256, 256>>>(pA,  256*256, 0);
    stats_kernel<<<256, 256>>>(s11, 256*256, 1);
    combine_kernel<<<1, 256>>>(256);
    wct_apply_kernel<<<(4*64*256*256)/256, 256>>>(pA, 16);
    conv11_kernel<<<dim3(16,16,4), 256>>>(pA, wT+offs[8], bsrc[8], outp, 256, 256);
}

// round 6
// speedup vs baseline: 1.0979x; 1.0979x over previous
#include <cuda_runtime.h>
#include <math.h>

// ======================= device scratch (no allocations allowed) ==========
#define BUF_ELEMS (4u*64u*256u*256u)   /* 16,777,216 floats = 64 MB */
__device__ float g_bufA[BUF_ELEMS];
__device__ float g_bufB[BUF_ELEMS];
__device__ float g_bufC[BUF_ELEMS];
__device__ float g_wT[3503808];        /* all transposed weights */
__device__ float g_cm[1024], g_cs[1024], g_sm[1024], g_ssd[1024];
__device__ float g_a[1024],  g_bsh[1024];
__device__ float g_blurk[12*81];

// ======================= packed f32x2 helpers =============================
__device__ __forceinline__ void ffma2(unsigned long long &d,
                                      unsigned long long a,
                                      unsigned long long b)
{
    asm("fma.rn.f32x2 %0, %1, %2, %0;" : "+l"(d) : "l"(a), "l"(b));
}
__device__ __forceinline__ unsigned long long dup2(float v)
{
    unsigned long long r;
    asm("mov.b64 %0, {%1, %1};" : "=l"(r) : "f"(v));
    return r;
}
__device__ __forceinline__ void unpack2(unsigned long long a, float &lo, float &hi)
{
    asm("mov.b64 {%0, %1}, %2;" : "=f"(lo), "=f"(hi) : "l"(a));
}

// ======================= weight transpose: [co][ci][9] -> [(ci*9+t)][co] ==
__global__ void transpose_w(const float* __restrict__ src, float* __restrict__ dst,
                            int Cin, int Cout)
{
    int idx = blockIdx.x * blockDim.x + threadIdx.x;
    int total = Cin * Cout * 9;
    if (idx >= total) return;
    int co = idx % Cout;
    int t  = (idx / Cout) % 9;
    int ci = idx / (Cout * 9);
    dst[idx] = src[((size_t)co * Cin + ci) * 9 + t];
}

// ======================= per-sample masked gaussian kernels ===============
__global__ void build_blur(const float* __restrict__ alphas)
{
    int i = threadIdx.x;        // 0..11 : b*3 + col
    if (i >= 12) return;
    float alpha = alphas[i];
    float k = floorf(floorf(alpha * 8.0f) * 0.5f) * 2.0f + 1.0f;
    float r = (k - 1.0f) * 0.5f;
    float vals[81];
    float sum = 0.0f;
    for (int y = 0; y < 9; y++)
        for (int x = 0; x < 9; x++) {
            float cy = (float)(y - 4), cx = (float)(x - 4);
            float g = expf(-(cy*cy + cx*cx) / 512.0f);
            float v = (fabsf(cy) <= r && fabsf(cx) <= r) ? g : 0.0f;
            vals[y*9 + x] = v;
            sum += v;
        }
    float inv = 1.0f / sum;
    for (int j = 0; j < 81; j++) g_blurk[i*81 + j] = vals[j] * inv;
}

// ======================= channel stats (mean + unbiased std) ==============
__global__ void stats_kernel(const float* __restrict__ x, int HW, int which)
{
    int bc = blockIdx.x;
    const float* p = x + (size_t)bc * HW;
    float s = 0.f, s2 = 0.f;
    for (int i = threadIdx.x; i < HW; i += blockDim.x) {
        float v = p[i];
        s += v;
        s2 = fmaf(v, v, s2);
    }
#pragma unroll
    for (int o = 16; o > 0; o >>= 1) {
        s  += __shfl_down_sync(0xffffffffu, s,  o);
        s2 += __shfl_down_sync(0xffffffffu, s2, o);
    }
    __shared__ float rs[8], rs2[8];
    int w = threadIdx.x >> 5, l = threadIdx.x & 31;
    if (l == 0) { rs[w] = s; rs2[w] = s2; }
    __syncthreads();
    if (threadIdx.x == 0) {
        float S = 0.f, S2 = 0.f;
        for (int i = 0; i < 8; i++) { S += rs[i]; S2 += rs2[i]; }
        float n = (float)HW;
        float mean = S / n;
        float var = (S2 - S * S / n) / (n - 1.0f);
        if (var < 0.f) var = 0.f;
        float sd = sqrtf(var);
        if (which == 0) { g_cm[bc] = mean; g_cs[bc]  = sd; }
        else            { g_sm[bc] = mean; g_ssd[bc] = sd; }
    }
}

__global__ void combine_kernel(int n)
{
    int i = blockIdx.x * blockDim.x + threadIdx.x;
    if (i >= n) return;
    float a = g_ssd[i] / (g_cs[i] + 1e-5f);
    g_a[i]   = a;
    g_bsh[i] = g_sm[i] - g_cm[i] * a;
}

__global__ void wct_apply_kernel(float* __restrict__ x, int sh)
{
    int idx = blockIdx.x * blockDim.x + threadIdx.x;
    int bc = idx >> sh;
    x[idx] = fmaf(x[idx], g_a[bc], g_bsh[bc]);
}

// hh = x - up2(avgpool2(x))
__global__ void hh_kernel(const float* __restrict__ x, float* __restrict__ o,
                          int wsh, int hsh)
{
    int idx = blockIdx.x * blockDim.x + threadIdx.x;
    int W = 1 << wsh;
    int xc = idx & (W - 1);
    int y  = (idx >> wsh) & ((1 << hsh) - 1);
    size_t chbase = ((size_t)(idx >> (wsh + hsh))) << (wsh + hsh);
    int y0 = y & ~1, x0 = xc & ~1;
    const float* ch = x + chbase;
    size_t b0 = (size_t)y0 * W + x0;
    float avg = 0.25f * (ch[b0] + ch[b0 + 1] + ch[b0 + W] + ch[b0 + W + 1]);
    o[idx] = x[idx] - avg;
}

// out = up2(small) + g_a[bc] * blur9x9(hh)   (replicate pad 4)
#define BT 16
__global__ void blur_add_kernel(const float* __restrict__ hh,
                                const float* __restrict__ small,
                                float* __restrict__ out,
                                int C, int H, int W, int lvl)
{
    int bc = blockIdx.z;
    int b  = bc / C;
    int ty0 = blockIdx.y * BT, tx0 = blockIdx.x * BT;
    __shared__ float tile[BT + 8][BT + 9];
    __shared__ float ker[81];
    int tid = threadIdx.x;
    if (tid < 81) ker[tid] = g_blurk[(b * 3 + lvl) * 81 + tid];
    const float* src = hh + (size_t)bc * H * W;
    for (int i = tid; i < (BT + 8) * (BT + 8); i += 256) {
        int r = i / (BT + 8), c = i % (BT + 8);
        int gy = ty0 - 4 + r; gy = gy < 0 ? 0 : (gy >= H ? H - 1 : gy);
        int gx = tx0 - 4 + c; gx = gx < 0 ? 0 : (gx >= W ? W - 1 : gx);
        tile[r][c] = src[(size_t)gy * W + gx];
    }
    __syncthreads();
    int ly = tid >> 4, lx = tid & 15;
    float s = 0.f;
#pragma unroll
    for (int dy = 0; dy < 9; dy++)
#pragma unroll
        for (int dx = 0; dx < 9; dx++)
            s = fmaf(ker[dy * 9 + dx], tile[ly + dy][lx + dx], s);
    int y = ty0 + ly, x = tx0 + lx;
    int W2 = W >> 1;
    size_t hw2 = (size_t)(H >> 1) * W2;
    float up = small[(size_t)bc * hw2 + (size_t)(y >> 1) * W2 + (x >> 1)];
    out[(size_t)bc * H * W + (size_t)y * W + x] = up + g_a[bc] * s;
}

// ======================= main conv3x3 v2 (FFMA2, reflect pad 1) ===========
// Block: 16x16 spatial tile x 32 output channels, 256 threads.
// Thread: 8 consecutive px (one row) x 4 co (as 2 co-pairs) -> 16 f32x2 accs.
#define TILE 16
#define COB  32
#define CCH  8
#define SROW 20   /* smem input row stride (floats) */
__global__ __launch_bounds__(256, 3)
void conv3x3_kernel(const float* __restrict__ in, const float* __restrict__ wT,
                    const float* __restrict__ bias, float* __restrict__ out,
                    int Cin, int Cout, int H, int W, int doRelu)
{
    const int nCoG = Cout / COB;
    const int b       = blockIdx.z / nCoG;
    const int co_base = (blockIdx.z % nCoG) * COB;
    const int ty0 = blockIdx.y * TILE;
    const int tx0 = blockIdx.x * TILE;

    const int tid  = threadIdx.x;
    const int co_t = tid >> 5;          // 0..7, one per warp
    const int px_t = tid & 31;
    const int y    = px_t >> 1;         // 0..15
    const int x0   = (px_t & 1) << 3;   // 0 or 8
    const int co4  = co_t << 2;         // base of 4 co handled by this thread

    __shared__ __align__(16) float sIn[CCH][TILE + 2][SROW];
    __shared__ __align__(16) float sW[CCH][9][COB];

    unsigned long long acc[8][2];
#pragma unroll
    for (int p = 0; p < 8; p++) { acc[p][0] = 0ull; acc[p][1] = 0ull; }

    const size_t chsz = (size_t)H * W;
    const float* inB = in + (size_t)b * Cin * chsz;

    for (int c0 = 0; c0 < Cin; c0 += CCH) {
        // ---- fill input tiles (reflect pad 1) ----
        for (int idx = tid; idx < CCH * (TILE + 2) * (TILE + 2); idx += 256) {
            int ci  = idx / ((TILE + 2) * (TILE + 2));
            int rem = idx - ci * ((TILE + 2) * (TILE + 2));
            int r = rem / (TILE + 2), c = rem - r * (TILE + 2);
            int gy = ty0 - 1 + r;
            int gx = tx0 - 1 + c;
            gy = gy < 0 ? -gy : (gy >= H ? 2 * H - 2 - gy : gy);
            gx = gx < 0 ? -gx : (gx >= W ? 2 * W - 2 - gx : gx);
            sIn[ci][r][c] = inB[(size_t)(c0 + ci) * chsz + (size_t)gy * W + gx];
        }
        // ---- fill weights: wT [(ci*9+t)*Cout + co], coalesced over co ----
        for (int idx = tid; idx < CCH * 9 * COB; idx += 256) {
            int ci = idx / (9 * COB); int rem = idx - ci * (9 * COB);
            int t = rem / COB; int co = rem - t * COB;
            sW[ci][t][co] = wT[((size_t)(c0 + ci) * 9 + t) * Cout + co_base + co];
        }
        __syncthreads();

        for (int ci = 0; ci < CCH; ci++) {
#pragma unroll
            for (int dy = 0; dy < 3; dy++) {
                const float* row = &sIn[ci][y + dy][x0];
                float4 v0 = *reinterpret_cast<const float4*>(row);
                float4 v1 = *reinterpret_cast<const float4*>(row + 4);
                float2 v2 = *reinterpret_cast<const float2*>(row + 8);
                unsigned long long rd[10];
                rd[0] = dup2(v0.x); rd[1] = dup2(v0.y);
                rd[2] = dup2(v0.z); rd[3] = dup2(v0.w);
                rd[4] = dup2(v1.x); rd[5] = dup2(v1.y);
                rd[6] = dup2(v1.z); rd[7] = dup2(v1.w);
                rd[8] = dup2(v2.x); rd[9] = dup2(v2.y);
#pragma unroll
                for (int dx = 0; dx < 3; dx++) {
                    const int t = dy * 3 + dx;
                    const unsigned long long* wp =
                        reinterpret_cast<const unsigned long long*>(&sW[ci][t][co4]);
                    unsigned long long w01 = wp[0];
                    unsigned long long w23 = wp[1];
#pragma unroll
                    for (int p = 0; p < 8; p++) {
                        ffma2(acc[p][0], rd[dx + p], w01);
                        ffma2(acc[p][1], rd[dx + p], w23);
                    }
                }
            }
        }
        __syncthreads();
    }

    // ---- epilogue: bias + relu + store ----
    float* outB = out + ((size_t)b * Cout + co_base) * chsz;
    float b0v = bias[co_base + co4 + 0];
    float b1v = bias[co_base + co4 + 1];
    float b2v = bias[co_base + co4 + 2];
    float b3v = bias[co_base + co4 + 3];
#pragma unroll
    for (int p = 0; p < 8; p++) {
        float f0, f1, f2, f3;
        unpack2(acc[p][0], f0, f1);
        unpack2(acc[p][1], f2, f3);
        f0 += b0v; f1 += b1v; f2 += b2v; f3 += b3v;
        if (doRelu) {
            f0 = fmaxf(f0, 0.f); f1 = fmaxf(f1, 0.f);
            f2 = fmaxf(f2, 0.f); f3 = fmaxf(f3, 0.f);
        }
        size_t off = (size_t)(ty0 + y) * W + (tx0 + x0 + p);
        outB[(size_t)(co4 + 0) * chsz + off] = f0;
        outB[(size_t)(co4 + 1) * chsz + off] = f1;
        outB[(size_t)(co4 + 2) * chsz + off] = f2;
        outB[(size_t)(co4 + 3) * chsz + off] = f3;
    }
}

// ======================= final conv (Cin=64, Cout=3, no relu) =============
__global__ __launch_bounds__(256)
void conv11_kernel(const float* __restrict__ in, const float* __restrict__ wT,
                   const float* __restrict__ bias, float* __restrict__ out,
                   int H, int W)
{
    int b = blockIdx.z;
    int ty0 = blockIdx.y * 16, tx0 = blockIdx.x * 16;
    __shared__ float sIn[8][18][18];
    __shared__ float sW[64 * 9 * 3];
    int tid = threadIdx.x;
    for (int i = tid; i < 64 * 9 * 3; i += 256) sW[i] = wT[i];
    float a0 = 0.f, a1 = 0.f, a2 = 0.f;
    int ly = tid >> 4, lx = tid & 15;
    const size_t chsz = (size_t)H * W;
    const float* inB = in + (size_t)b * 64 * chsz;
    for (int c0 = 0; c0 < 64; c0 += 8) {
        __syncthreads();
        for (int i = tid; i < 8 * 324; i += 256) {
            int ci = i / 324; int rem = i - ci * 324;
            int r = rem / 18, c = rem - r * 18;
            int gy = ty0 - 1 + r; gy = gy < 0 ? -gy : (gy >= H ? 2 * H - 2 - gy : gy);
            int gx = tx0 - 1 + c; gx = gx < 0 ? -gx : (gx >= W ? 2 * W - 2 - gx : gx);
            sIn[ci][r][c] = inB[(size_t)(c0 + ci) * chsz + (size_t)gy * W + gx];
        }
        __syncthreads();
        for (int ci = 0; ci < 8; ci++) {
#pragma unroll
            for (int t = 0; t < 9; t++) {
                float v = sIn[ci][ly + t / 3][lx + t % 3];
                int wb = ((c0 + ci) * 9 + t) * 3;
                a0 = fmaf(v, sW[wb + 0], a0);
                a1 = fmaf(v, sW[wb + 1], a1);
                a2 = fmaf(v, sW[wb + 2], a2);
            }
        }
    }
    int y = ty0 + ly, x = tx0 + lx;
    size_t off = (size_t)y * W + x;
    out[((size_t)b * 3 + 0) * chsz + off] = a0 + bias[0];
    out[((size_t)b * 3 + 1) * chsz + off] = a1 + bias[1];
    out[((size_t)b * 3 + 2) * chsz + off] = a2 + bias[2];
}

// ======================= host launcher ====================================
extern "C" void kernel_launch(void* const* d_in, const int* in_sizes, int n_in,
                              void* d_out, int out_size)
{
    const float* x   = (const float*)d_in[0];
    const float* c34 = (const float*)d_in[1];
    const float* c22 = (const float*)d_in[2];
    const float* c12 = (const float*)d_in[3];
    const float* s34 = (const float*)d_in[4];
    const float* s31 = (const float*)d_in[5];
    const float* s22 = (const float*)d_in[6];
    const float* s21 = (const float*)d_in[7];
    const float* s12 = (const float*)d_in[8];
    const float* s11 = (const float*)d_in[9];
    const float* alphas = (const float*)d_in[10];
    const float* wsrc[9] = { (const float*)d_in[11], (const float*)d_in[13],
                             (const float*)d_in[15], (const float*)d_in[17],
                             (const float*)d_in[19], (const float*)d_in[21],
                             (const float*)d_in[23], (const float*)d_in[25],
                             (const float*)d_in[27] };
    const float* bsrc[9] = { (const float*)d_in[12], (const float*)d_in[14],
                             (const float*)d_in[16], (const float*)d_in[18],
                             (const float*)d_in[20], (const float*)d_in[22],
                             (const float*)d_in[24], (const float*)d_in[26],
                             (const float*)d_in[28] };
    float* outp = (float*)d_out;

    float *pA, *pB, *pC, *wT;
    cudaGetSymbolAddress((void**)&pA, g_bufA);
    cudaGetSymbolAddress((void**)&pB, g_bufB);
    cudaGetSymbolAddress((void**)&pC, g_bufC);
    cudaGetSymbolAddress((void**)&wT, g_wT);

    const int cins[9]  = {512,256,256,256,256,128,128,64,64};
    const int couts[9] = {256,256,256,256,128,128, 64,64, 3};
    size_t offs[9]; size_t off = 0;
    for (int l = 0; l < 9; l++) { offs[l] = off; off += (size_t)cins[l]*couts[l]*9; }
    for (int l = 0; l < 9; l++) {
        int total = cins[l]*couts[l]*9;
        transpose_w<<<(total + 255)/256, 256>>>(wsrc[l], wT + offs[l], cins[l], couts[l]);
    }
    build_blur<<<1, 32>>>(alphas);

    // ---- level 4 -> 3 ----
    conv3x3_kernel<<<dim3(2,2,32), 256>>>(x, wT+offs[0], bsrc[0], pA, 512,256,32,32, 1);
    stats_kernel<<<1024, 256>>>(c34, 64*64, 0);
    stats_kernel<<<1024, 256>>>(s34, 64*64, 1);
    combine_kernel<<<4, 256>>>(1024);
    hh_kernel<<<(4*256*64*64)/256, 256>>>(c34, pC, 6, 6);
    blur_add_kernel<<<dim3(4,4,1024), 256>>>(pC, pA, pB, 256, 64, 64, 2);
    conv3x3_kernel<<<dim3(4,4,32), 256>>>(pB, wT+offs[1], bsrc[1], pA, 256,256,64,64, 1);
    conv3x3_kernel<<<dim3(4,4,32), 256>>>(pA, wT+offs[2], bsrc[2], pB, 256,256,64,64, 1);
    conv3x3_kernel<<<dim3(4,4,32), 256>>>(pB, wT+offs[3], bsrc[3], pA, 256,256,64,64, 1);
    stats_kernel<<<1024, 256>>>(pA,  64*64, 0);
    stats_kernel<<<1024, 256>>>(s31, 64*64, 1);
    combine_kernel<<<4, 256>>>(1024);
    wct_apply_kernel<<<(4*256*64*64)/256, 256>>>(pA, 12);
    conv3x3_kernel<<<dim3(4,4,16), 256>>>(pA, wT+offs[4], bsrc[4], pB, 256,128,64,64, 1);

    // ---- level 3 -> 2 ----
    stats_kernel<<<512, 256>>>(c22, 128*128, 0);
    stats_kernel<<<512, 256>>>(s22, 128*128, 1);
    combine_kernel<<<2, 256>>>(512);
    hh_kernel<<<(4*128*128*128)/256, 256>>>(c22, pC, 7, 7);
    blur_add_kernel<<<dim3(8,8,512), 256>>>(pC, pB, pA, 128, 128, 128, 1);
    conv3x3_kernel<<<dim3(8,8,16), 256>>>(pA, wT+offs[5], bsrc[5], pB, 128,128,128,128, 1);
    stats_kernel<<<512, 256>>>(pB,  128*128, 0);
    stats_kernel<<<512, 256>>>(s21, 128*128, 1);
    combine_kernel<<<2, 256>>>(512);
    wct_apply_kernel<<<(4*128*128*128)/256, 256>>>(pB, 14);
    conv3x3_kernel<<<dim3(8,8,8), 256>>>(pB, wT+offs[6], bsrc[6], pA, 128,64,128,128, 1);

    // ---- level 2 -> 1 ----
    stats_kernel<<<256, 256>>>(c12, 256*256, 0);
    stats_kernel<<<256, 256>>>(s12, 256*256, 1);
    combine_kernel<<<1, 256>>>(256);
    hh_kernel<<<(4*64*256*256)/256, 256>>>(c12, pC, 8, 8);
    blur_add_kernel<<<dim3(16,16,256), 256>>>(pC, pA, pB, 64, 256, 256, 0);
    conv3x3_kernel<<<dim3(16,16,8), 256>>>(pB, wT+offs[7], bsrc[7], pA, 64,64,256,256, 1);
    stats_kernel<<<256, 256>>>(pA,  256*256, 0);
    stats_kernel<<<256, 256>>>(s11, 256*256, 1);
    combine_kernel<<<1, 256>>>(256);
    wct_apply_kernel<<<(4*64*256*256)/256, 256>>>(pA, 16);
    conv11_kernel<<<dim3(16,16,4), 256>>>(pA, wT+offs[8], bsrc[8], outp, 256, 256);
}

// round 11
// speedup vs baseline: 1.2719x; 1.1584x over previous
#include <cuda_runtime.h>
#include <cuda_bf16.h>
#include <math.h>
#include <stdint.h>

// ======================= device scratch (no allocations allowed) ==========
#define BUF_ELEMS (4u*64u*256u*256u)   /* 16,777,216 floats = 64 MB */
__device__ float g_bufA[BUF_ELEMS];
__device__ float g_bufB[BUF_ELEMS];
__device__ float g_bufC[BUF_ELEMS];
__device__ __align__(16) __nv_bfloat16 g_wHi[3502080];
__device__ __align__(16) __nv_bfloat16 g_wLo[3502080];
__device__ float g_wT[64*9*3 + 64];    /* transposed conv11 weights */
__device__ float g_cm[1024], g_cs[1024], g_sm[1024], g_ssd[1024];
__device__ float g_a[1024],  g_bsh[1024];
__device__ float g_blurk[12*81];

// ======================= PTX helpers =====================================
__device__ __forceinline__ uint32_t smem_u32(const void* p) {
    uint32_t a;
    asm("{ .reg .u64 t; cvta.to.shared.u64 t, %1; cvt.u32.u64 %0, t; }"
        : "=r"(a) : "l"(p));
    return a;
}
__device__ __forceinline__ void ldsm4(uint32_t* r, uint32_t addr) {
    asm volatile("ldmatrix.sync.aligned.m8n8.x4.shared.b16 {%0,%1,%2,%3}, [%4];"
        : "=r"(r[0]), "=r"(r[1]), "=r"(r[2]), "=r"(r[3]) : "r"(addr));
}
__device__ __forceinline__ void mma16816(float* d, const uint32_t* a,
                                         const uint32_t* b) {
    asm volatile(
        "mma.sync.aligned.m16n8k16.row.col.f32.bf16.bf16.f32 "
        "{%0,%1,%2,%3}, {%4,%5,%6,%7}, {%8,%9}, {%0,%1,%2,%3};"
        : "+f"(d[0]), "+f"(d[1]), "+f"(d[2]), "+f"(d[3])
        : "r"(a[0]), "r"(a[1]), "r"(a[2]), "r"(a[3]), "r"(b[0]), "r"(b[1]));
}

// ======================= weight prep =====================================
// dst layout: [tap][ch][co][ci64]
__global__ void prep_w(const float* __restrict__ src,
                       __nv_bfloat16* __restrict__ hi,
                       __nv_bfloat16* __restrict__ lo,
                       int Cin, int Cout)
{
    int idx = blockIdx.x * blockDim.x + threadIdx.x;
    int total = Cin * Cout * 9;
    if (idx >= total) return;
    int ci_in = idx & 63;
    int rest  = idx >> 6;
    int co    = rest % Cout;
    int rest2 = rest / Cout;
    int nch   = Cin >> 6;
    int ch    = rest2 % nch;
    int tap   = rest2 / nch;
    float v = src[((size_t)co * Cin + ch * 64 + ci_in) * 9 + tap];
    __nv_bfloat16 h = __float2bfloat16(v);
    hi[idx] = h;
    lo[idx] = __float2bfloat16(v - __bfloat162float(h));
}

// conv11 weight transpose: [co][ci][9] -> [(ci*9+t)*3 + co]
__global__ void transpose_w(const float* __restrict__ src, float* __restrict__ dst,
                            int Cin, int Cout)
{
    int idx = blockIdx.x * blockDim.x + threadIdx.x;
    int total = Cin * Cout * 9;
    if (idx >= total) return;
    int co = idx % Cout;
    int t  = (idx / Cout) % 9;
    int ci = idx / (Cout * 9);
    dst[idx] = src[((size_t)co * Cin + ci) * 9 + t];
}

// ======================= per-sample masked gaussian kernels ===============
__global__ void build_blur(const float* __restrict__ alphas)
{
    int i = threadIdx.x;
    if (i >= 12) return;
    float alpha = alphas[i];
    float k = floorf(floorf(alpha * 8.0f) * 0.5f) * 2.0f + 1.0f;
    float r = (k - 1.0f) * 0.5f;
    float vals[81];
    float sum = 0.0f;
    for (int y = 0; y < 9; y++)
        for (int x = 0; x < 9; x++) {
            float cy = (float)(y - 4), cx = (float)(x - 4);
            float g = expf(-(cy*cy + cx*cx) / 512.0f);
            float v = (fabsf(cy) <= r && fabsf(cx) <= r) ? g : 0.0f;
            vals[y*9 + x] = v;
            sum += v;
        }
    float inv = 1.0f / sum;
    for (int j = 0; j < 81; j++) g_blurk[i*81 + j] = vals[j] * inv;
}

// ======================= channel stats (mean + unbiased std) ==============
__global__ void stats_kernel(const float* __restrict__ x, int HW, int which)
{
    int bc = blockIdx.x;
    const float* p = x + (size_t)bc * HW;
    float s = 0.f, s2 = 0.f;
    for (int i = threadIdx.x; i < HW; i += blockDim.x) {
        float v = p[i];
        s += v;
        s2 = fmaf(v, v, s2);
    }
#pragma unroll
    for (int o = 16; o > 0; o >>= 1) {
        s  += __shfl_down_sync(0xffffffffu, s,  o);
        s2 += __shfl_down_sync(0xffffffffu, s2, o);
    }
    __shared__ float rs[8], rs2[8];
    int w = threadIdx.x >> 5, l = threadIdx.x & 31;
    if (l == 0) { rs[w] = s; rs2[w] = s2; }
    __syncthreads();
    if (threadIdx.x == 0) {
        float S = 0.f, S2 = 0.f;
        for (int i = 0; i < 8; i++) { S += rs[i]; S2 += rs2[i]; }
        float n = (float)HW;
        float mean = S / n;
        float var = (S2 - S * S / n) / (n - 1.0f);
        if (var < 0.f) var = 0.f;
        float sd = sqrtf(var);
        if (which == 0) { g_cm[bc] = mean; g_cs[bc]  = sd; }
        else            { g_sm[bc] = mean; g_ssd[bc] = sd; }
    }
}

__global__ void combine_kernel(int n)
{
    int i = blockIdx.x * blockDim.x + threadIdx.x;
    if (i >= n) return;
    float a = g_ssd[i] / (g_cs[i] + 1e-5f);
    g_a[i]   = a;
    g_bsh[i] = g_sm[i] - g_cm[i] * a;
}

__global__ void wct_apply_kernel(float* __restrict__ x, int sh)
{
    int idx = blockIdx.x * blockDim.x + threadIdx.x;
    int bc = idx >> sh;
    x[idx] = fmaf(x[idx], g_a[bc], g_bsh[bc]);
}

// hh = x - up2(avgpool2(x))
__global__ void hh_kernel(const float* __restrict__ x, float* __restrict__ o,
                          int wsh, int hsh)
{
    int idx = blockIdx.x * blockDim.x + threadIdx.x;
    int W = 1 << wsh;
    int xc = idx & (W - 1);
    int y  = (idx >> wsh) & ((1 << hsh) - 1);
    size_t chbase = ((size_t)(idx >> (wsh + hsh))) << (wsh + hsh);
    int y0 = y & ~1, x0 = xc & ~1;
    const float* ch = x + chbase;
    size_t b0 = (size_t)y0 * W + x0;
    float avg = 0.25f * (ch[b0] + ch[b0 + 1] + ch[b0 + W] + ch[b0 + W + 1]);
    o[idx] = x[idx] - avg;
}

// out = up2(small) + g_a[bc] * blur9x9(hh)   (replicate pad 4)
#define BT 16
__global__ void blur_add_kernel(const float* __restrict__ hh,
                                const float* __restrict__ small,
                                float* __restrict__ out,
                                int C, int H, int W, int lvl)
{
    int bc = blockIdx.z;
    int b  = bc / C;
    int ty0 = blockIdx.y * BT, tx0 = blockIdx.x * BT;
    __shared__ float tile[BT + 8][BT + 9];
    __shared__ float ker[81];
    int tid = threadIdx.x;
    if (tid < 81) ker[tid] = g_blurk[(b * 3 + lvl) * 81 + tid];
    const float* src = hh + (size_t)bc * H * W;
    for (int i = tid; i < (BT + 8) * (BT + 8); i += 256) {
        int r = i / (BT + 8), c = i % (BT + 8);
        int gy = ty0 - 4 + r; gy = gy < 0 ? 0 : (gy >= H ? H - 1 : gy);
        int gx = tx0 - 4 + c; gx = gx < 0 ? 0 : (gx >= W ? W - 1 : gx);
        tile[r][c] = src[(size_t)gy * W + gx];
    }
    __syncthreads();
    int ly = tid >> 4, lx = tid & 15;
    float s = 0.f;
#pragma unroll
    for (int dy = 0; dy < 9; dy++)
#pragma unroll
        for (int dx = 0; dx < 9; dx++)
            s = fmaf(ker[dy * 9 + dx], tile[ly + dy][lx + dx], s);
    int y = ty0 + ly, x = tx0 + lx;
    int W2 = W >> 1;
    size_t hw2 = (size_t)(H >> 1) * W2;
    float up = small[(size_t)bc * hw2 + (size_t)(y >> 1) * W2 + (x >> 1)];
    out[(size_t)bc * H * W + (size_t)y * W + x] = up + g_a[bc] * s;
}

// ======================= mma.sync conv3x3 =================================
// Block: 128 px (16x8) x 64 co, 256 threads, 8 warps (4 M x 2 N).
// Halo converted to bf16 hi/lo once per 64-ci chunk, stored [pos][ci64]
// (144 B stride). Per tap: ldmatrix at shifted pos + 24 mma per k16 step.
#define OFF_AHI 0
#define OFF_ALO 25920
#define OFF_BHI 51840
#define OFF_BLO 61056
#define SMEM_SZ 70272

__global__ __launch_bounds__(256, 2)
void conv_mma_kernel(const float* __restrict__ in,
                     const __nv_bfloat16* __restrict__ wHi,
                     const __nv_bfloat16* __restrict__ wLo,
                     const float* __restrict__ bias,
                     float* __restrict__ out,
                     int Cin, int Cout, int H, int W, int doRelu)
{
    extern __shared__ __align__(16) char smem[];
    const uint32_t sb = smem_u32(smem);
    __nv_bfloat16* haloHi = (__nv_bfloat16*)(smem + OFF_AHI);
    __nv_bfloat16* haloLo = (__nv_bfloat16*)(smem + OFF_ALO);

    const int tid  = threadIdx.x;
    const int lane = tid & 31;
    const int wid  = tid >> 5;
    const int warp_m = wid & 3;     // px group (32 px)
    const int warp_n = wid >> 2;    // co group (32 co)

    const int cog     = Cout >> 6;
    const int b       = blockIdx.z / cog;
    const int co_base = (blockIdx.z % cog) << 6;
    const int x0 = blockIdx.x * 16;
    const int y0 = blockIdx.y * 8;
    const size_t chsz = (size_t)H * W;
    const float* inB = in + (size_t)b * Cin * chsz;
    const int nch = Cin >> 6;

    float acc[2][4][4];
#pragma unroll
    for (int mi = 0; mi < 2; mi++)
#pragma unroll
        for (int ni = 0; ni < 4; ni++)
#pragma unroll
            for (int q = 0; q < 4; q++) acc[mi][ni][q] = 0.f;

    // per-thread ldmatrix addressing constants
    const int aR = lane & 15, aK = lane >> 4;            // A: row px, k-half
    const int bN = (((lane >> 4) & 1) << 3) | (lane & 7); // B: n row
    const int bK = (lane >> 3) & 1;                       // B: k-half

    for (int ch = 0; ch < nch; ch++) {
        __syncthreads();
        // ---- halo fill: fp32 gmem (reflect pad) -> bf16 hi/lo [pos][ci] ----
        for (int idx = tid; idx < 64 * 180; idx += 256) {
            int ci  = idx / 180;
            int pos = idx - ci * 180;
            int r = pos / 18, c = pos - r * 18;
            int gy = y0 - 1 + r; gy = gy < 0 ? -gy : (gy >= H ? 2*H - 2 - gy : gy);
            int gx = x0 - 1 + c; gx = gx < 0 ? -gx : (gx >= W ? 2*W - 2 - gx : gx);
            float v = inB[(size_t)(ch * 64 + ci) * chsz + (size_t)gy * W + gx];
            __nv_bfloat16 h = __float2bfloat16(v);
            haloHi[pos * 72 + ci] = h;
            haloLo[pos * 72 + ci] = __float2bfloat16(v - __bfloat162float(h));
        }

        for (int tap = 0; tap < 9; tap++) {
            __syncthreads();
            // ---- B fill: [tap][ch][co][ci64] -> smem [co][ci64] (144B rows)
            {
                const __nv_bfloat16* gHi =
                    wHi + ((size_t)(tap * nch + ch) * Cout + co_base) * 64;
                const __nv_bfloat16* gLo =
                    wLo + ((size_t)(tap * nch + ch) * Cout + co_base) * 64;
                const uint4* ghi4 = (const uint4*)gHi;
                const uint4* glo4 = (const uint4*)gLo;
                for (int idx = tid; idx < 512; idx += 256) {
                    int co = idx >> 3, g = idx & 7;
                    uint32_t ad = co * 144 + g * 16;
                    *(uint4*)(smem + OFF_BHI + ad) = ghi4[idx];
                    *(uint4*)(smem + OFF_BLO + ad) = glo4[idx];
                }
            }
            __syncthreads();

            // ---- compute ----
            const int dy = tap / 3, dx = tap - 3 * (tap / 3);
            const uint32_t aBase = sb + OFF_AHI +
                (uint32_t)(((2*warp_m + dy) * 18 + aR + dx) * 144 + aK * 16);
            const uint32_t bBase = sb + OFF_BHI +
                (uint32_t)((warp_n * 32 + bN) * 144 + bK * 16);

#pragma unroll
            for (int ks = 0; ks < 4; ks++) {
                const uint32_t ko = ks * 32;
                uint32_t ahi[2][4], alo[2][4], bhi[4], blo[4], bhi2[4], blo2[4];
                ldsm4(ahi[0], aBase + ko);
                ldsm4(ahi[1], aBase + ko + 18*144);
                ldsm4(alo[0], aBase + ko + (OFF_ALO - OFF_AHI));
                ldsm4(alo[1], aBase + ko + (OFF_ALO - OFF_AHI) + 18*144);
                ldsm4(bhi,  bBase + ko);
                ldsm4(bhi2, bBase + ko + 16*144);
                ldsm4(blo,  bBase + ko + (OFF_BLO - OFF_BHI));
                ldsm4(blo2, bBase + ko + (OFF_BLO - OFF_BHI) + 16*144);
                // B frags: ni0={bhi[0],bhi[1]}, ni1={bhi[2],bhi[3]},
                //          ni2={bhi2[0],bhi2[1]}, ni3={bhi2[2],bhi2[3]}
#pragma unroll
                for (int mi = 0; mi < 2; mi++) {
                    mma16816(acc[mi][0], ahi[mi], bhi);
                    mma16816(acc[mi][1], ahi[mi], bhi + 2);
                    mma16816(acc[mi][2], ahi[mi], bhi2);
                    mma16816(acc[mi][3], ahi[mi], bhi2 + 2);
                    mma16816(acc[mi][0], ahi[mi], blo);
                    mma16816(acc[mi][1], ahi[mi], blo + 2);
                    mma16816(acc[mi][2], ahi[mi], blo2);
                    mma16816(acc[mi][3], ahi[mi], blo2 + 2);
                    mma16816(acc[mi][0], alo[mi], bhi);
                    mma16816(acc[mi][1], alo[mi], bhi + 2);
                    mma16816(acc[mi][2], alo[mi], bhi2);
                    mma16816(acc[mi][3], alo[mi], bhi2 + 2);
                }
            }
        }
    }

    // ---- epilogue: bias + relu + store ----
    const int xr = lane >> 2;
    const int c0 = (lane & 3) << 1;
#pragma unroll
    for (int ni = 0; ni < 4; ni++) {
        int co = co_base + warp_n * 32 + ni * 8 + c0;
        float bv0 = __ldg(&bias[co]);
        float bv1 = __ldg(&bias[co + 1]);
        float* o0 = out + ((size_t)b * Cout + co) * chsz;
        float* o1 = o0 + chsz;
#pragma unroll
        for (int mi = 0; mi < 2; mi++) {
            int yy = y0 + 2 * warp_m + mi;
            size_t rb = (size_t)yy * W + x0;
            float v0 = acc[mi][ni][0] + bv0;
            float v1 = acc[mi][ni][1] + bv1;
            float v2 = acc[mi][ni][2] + bv0;
            float v3 = acc[mi][ni][3] + bv1;
            if (doRelu) {
                v0 = fmaxf(v0, 0.f); v1 = fmaxf(v1, 0.f);
                v2 = fmaxf(v2, 0.f); v3 = fmaxf(v3, 0.f);
            }
            o0[rb + xr]     = v0;
            o1[rb + xr]     = v1;
            o0[rb + xr + 8] = v2;
            o1[rb + xr + 8] = v3;
        }
    }
}

// ======================= final conv (Cin=64, Cout=3, no relu) =============
__global__ __launch_bounds__(256)
void conv11_kernel(const float* __restrict__ in, const float* __restrict__ wT,
                   const float* __restrict__ bias, float* __restrict__ out,
                   int H, int W)
{
    int b = blockIdx.z;
    int ty0 = blockIdx.y * 16, tx0 = blockIdx.x * 16;
    __shared__ float sIn[8][18][18];
    __shared__ float sW[64 * 9 * 3];
    int tid = threadIdx.x;
    for (int i = tid; i < 64 * 9 * 3; i += 256) sW[i] = wT[i];
    float a0 = 0.f, a1 = 0.f, a2 = 0.f;
    int ly = tid >> 4, lx = tid & 15;
    const size_t chsz = (size_t)H * W;
    const float* inB = in + (size_t)b * 64 * chsz;
    for (int c0 = 0; c0 < 64; c0 += 8) {
        __syncthreads();
        for (int i = tid; i < 8 * 324; i += 256) {
            int ci = i / 324; int rem = i - ci * 324;
            int r = rem / 18, c = rem - r * 18;
            int gy = ty0 - 1 + r; gy = gy < 0 ? -gy : (gy >= H ? 2*H - 2 - gy : gy);
            int gx = tx0 - 1 + c; gx = gx < 0 ? -gx : (gx >= W ? 2*W - 2 - gx : gx);
            sIn[ci][r][c] = inB[(size_t)(c0 + ci) * chsz + (size_t)gy * W + gx];
        }
        __syncthreads();
        for (int ci = 0; ci < 8; ci++) {
#pragma unroll
            for (int t = 0; t < 9; t++) {
                float v = sIn[ci][ly + t / 3][lx + t % 3];
                int wb = ((c0 + ci) * 9 + t) * 3;
                a0 = fmaf(v, sW[wb + 0], a0);
                a1 = fmaf(v, sW[wb + 1], a1);
                a2 = fmaf(v, sW[wb + 2], a2);
            }
        }
    }
    int y = ty0 + ly, x = tx0 + lx;
    size_t off = (size_t)y * W + x;
    out[((size_t)b * 3 + 0) * chsz + off] = a0 + bias[0];
    out[((size_t)b * 3 + 1) * chsz + off] = a1 + bias[1];
    out[((size_t)b * 3 + 2) * chsz + off] = a2 + bias[2];
}

// ======================= host launcher ====================================
extern "C" void kernel_launch(void* const* d_in, const int* in_sizes, int n_in,
                              void* d_out, int out_size)
{
    const float* x   = (const float*)d_in[0];
    const float* c34 = (const float*)d_in[1];
    const float* c22 = (const float*)d_in[2];
    const float* c12 = (const float*)d_in[3];
    const float* s34 = (const float*)d_in[4];
    const float* s31 = (const float*)d_in[5];
    const float* s22 = (const float*)d_in[6];
    const float* s21 = (const float*)d_in[7];
    const float* s12 = (const float*)d_in[8];
    const float* s11 = (const float*)d_in[9];
    const float* alphas = (const float*)d_in[10];
    const float* wsrc[9] = { (const float*)d_in[11], (const float*)d_in[13],
                             (const float*)d_in[15], (const float*)d_in[17],
                             (const float*)d_in[19], (const float*)d_in[21],
                             (const float*)d_in[23], (const float*)d_in[25],
                             (const float*)d_in[27] };
    const float* bsrc[9] = { (const float*)d_in[12], (const float*)d_in[14],
                             (const float*)d_in[16], (const float*)d_in[18],
                             (const float*)d_in[20], (const float*)d_in[22],
                             (const float*)d_in[24], (const float*)d_in[26],
                             (const float*)d_in[28] };
    float* outp = (float*)d_out;

    float *pA, *pB, *pC, *wT;
    __nv_bfloat16 *wHi, *wLo;
    cudaGetSymbolAddress((void**)&pA, g_bufA);
    cudaGetSymbolAddress((void**)&pB, g_bufB);
    cudaGetSymbolAddress((void**)&pC, g_bufC);
    cudaGetSymbolAddress((void**)&wT, g_wT);
    cudaGetSymbolAddress((void**)&wHi, g_wHi);
    cudaGetSymbolAddress((void**)&wLo, g_wLo);

    cudaFuncSetAttribute(conv_mma_kernel,
                         cudaFuncAttributeMaxDynamicSharedMemorySize, SMEM_SZ);

    // weight prep (layers 0..7 use mma; layer 8 = conv11 stays scalar)
    const int cins[8]  = {512,256,256,256,256,128,128,64};
    const int couts[8] = {256,256,256,256,128,128, 64,64};
    size_t offs[8]; size_t off = 0;
    for (int l = 0; l < 8; l++) { offs[l] = off; off += (size_t)cins[l]*couts[l]*9; }
    for (int l = 0; l < 8; l++) {
        int total = cins[l]*couts[l]*9;
        prep_w<<<(total + 255)/256, 256>>>(wsrc[l], wHi + offs[l], wLo + offs[l],
                                           cins[l], couts[l]);
    }
    transpose_w<<<(64*3*9 + 255)/256, 256>>>(wsrc[8], wT, 64, 3);
    build_blur<<<1, 32>>>(alphas);

    auto conv = [&](const float* in, int l, const float* bias, float* out,
                    int H, int W) {
        int Cin = cins[l], Cout = couts[l];
        dim3 g(W/16, H/8, 4 * (Cout/64));
        conv_mma_kernel<<<g, 256, SMEM_SZ>>>(in, wHi + offs[l], wLo + offs[l],
                                             bias, out, Cin, Cout, H, W, 1);
    };

    // ---- level 4 -> 3 ----
    conv(x, 0, bsrc[0], pA, 32, 32);
    stats_kernel<<<1024, 256>>>(c34, 64*64, 0);
    stats_kernel<<<1024, 256>>>(s34, 64*64, 1);
    combine_kernel<<<4, 256>>>(1024);
    hh_kernel<<<(4*256*64*64)/256, 256>>>(c34, pC, 6, 6);
    blur_add_kernel<<<dim3(4,4,1024), 256>>>(pC, pA, pB, 256, 64, 64, 2);
    conv(pB, 1, bsrc[1], pA, 64, 64);
    conv(pA, 2, bsrc[2], pB, 64, 64);
    conv(pB, 3, bsrc[3], pA, 64, 64);
    stats_kernel<<<1024, 256>>>(pA,  64*64, 0);
    stats_kernel<<<1024, 256>>>(s31, 64*64, 1);
    combine_kernel<<<4, 256>>>(1024);
    wct_apply_kernel<<<(4*256*64*64)/256, 256>>>(pA, 12);
    conv(pA, 4, bsrc[4], pB, 64, 64);

    // ---- level 3 -> 2 ----
    stats_kernel<<<512, 256>>>(c22, 128*128, 0);
    stats_kernel<<<512, 256>>>(s22, 128*128, 1);
    combine_kernel<<<2, 256>>>(512);
    hh_kernel<<<(4*128*128*128)/256, 256>>>(c22, pC, 7, 7);
    blur_add_kernel<<<dim3(8,8,512), 256>>>(pC, pB, pA, 128, 128, 128, 1);
    conv(pA, 5, bsrc[5], pB, 128, 128);
    stats_kernel<<<512, 256>>>(pB,  128*128, 0);
    stats_kernel<<<512, 256>>>(s21, 128*128, 1);
    combine_kernel<<<2, 256>>>(512);
    wct_apply_kernel<<<(4*128*128*128)/256, 256>>>(pB, 14);
    conv(pB, 6, bsrc[6], pA, 128, 128);

    // ---- level 2 -> 1 ----
    stats_kernel<<<256, 256>>>(c12, 256*256, 0);
    stats_kernel<<<256, 256>>>(s12, 256*256, 1);
    combine_kernel<<<1, 256>>>(256);
    hh_kernel<<<(4*64*256*256)/256, 256>>>(c12, pC, 8, 8);
    blur_add_kernel<<<dim3(16,16,256), 256>>>(pC, pA, pB, 64, 256, 256, 0);
    conv(pB, 7, bsrc[7], pA, 256, 256);
    stats_kernel<<<256, 256>>>(pA,  256*256, 0);
    stats_kernel<<<256, 256>>>(s11, 256*256, 1);
    combine_kernel<<<1, 256>>>(256);
    wct_apply_kernel<<<(4*64*256*256)/256, 256>>>(pA, 16);
    conv11_kernel<<<dim3(16,16,4), 256>>>(pA, wT, bsrc[8], outp, 256, 256);
}

// round 12
// speedup vs baseline: 1.9464x; 1.5304x over previous
#include <cuda_runtime.h>
#include <cuda_bf16.h>
#include <math.h>
#include <stdint.h>

// ======================= device scratch (no allocations allowed) ==========
#define BUF_ELEMS (4u*64u*256u*256u)   /* 16,777,216 floats = 64 MB */
__device__ float g_bufA[BUF_ELEMS];
__device__ float g_bufB[BUF_ELEMS];
__device__ float g_bufC[BUF_ELEMS];
__device__ __align__(16) __nv_bfloat16 g_wHi[3502080];
__device__ __align__(16) __nv_bfloat16 g_wLo[3502080];
__device__ float g_wT[64*9*3 + 64];    /* transposed conv11 weights */
__device__ float g_cm[1024], g_cs[1024], g_sm[1024], g_ssd[1024];
__device__ float g_a[1024],  g_bsh[1024];
__device__ float g_blurk[12*81];

// ======================= PTX helpers =====================================
__device__ __forceinline__ uint32_t smem_u32(const void* p) {
    uint32_t a;
    asm("{ .reg .u64 t; cvta.to.shared.u64 t, %1; cvt.u32.u64 %0, t; }"
        : "=r"(a) : "l"(p));
    return a;
}
__device__ __forceinline__ void ldsm4(uint32_t* r, uint32_t addr) {
    asm volatile("ldmatrix.sync.aligned.m8n8.x4.shared.b16 {%0,%1,%2,%3}, [%4];"
        : "=r"(r[0]), "=r"(r[1]), "=r"(r[2]), "=r"(r[3]) : "r"(addr));
}
__device__ __forceinline__ void mma16816(float* d, const uint32_t* a,
                                         const uint32_t* b) {
    asm volatile(
        "mma.sync.aligned.m16n8k16.row.col.f32.bf16.bf16.f32 "
        "{%0,%1,%2,%3}, {%4,%5,%6,%7}, {%8,%9}, {%0,%1,%2,%3};"
        : "+f"(d[0]), "+f"(d[1]), "+f"(d[2]), "+f"(d[3])
        : "r"(a[0]), "r"(a[1]), "r"(a[2]), "r"(a[3]), "r"(b[0]), "r"(b[1]));
}
#define CP_ASYNC16(dst, src) \
    asm volatile("cp.async.cg.shared.global [%0], [%1], 16;" \
                 :: "r"(dst), "l"(src) : "memory")
#define CP_COMMIT() asm volatile("cp.async.commit_group;" ::: "memory")
#define CP_WAIT0()  asm volatile("cp.async.wait_group 0;" ::: "memory")

// ======================= weight prep =====================================
// dst layout: [tap][ch][co][ci64]
__global__ void prep_w(const float* __restrict__ src,
                       __nv_bfloat16* __restrict__ hi,
                       __nv_bfloat16* __restrict__ lo,
                       int Cin, int Cout)
{
    int idx = blockIdx.x * blockDim.x + threadIdx.x;
    int total = Cin * Cout * 9;
    if (idx >= total) return;
    int ci_in = idx & 63;
    int rest  = idx >> 6;
    int co    = rest % Cout;
    int rest2 = rest / Cout;
    int nch   = Cin >> 6;
    int ch    = rest2 % nch;
    int tap   = rest2 / nch;
    float v = src[((size_t)co * Cin + ch * 64 + ci_in) * 9 + tap];
    __nv_bfloat16 h = __float2bfloat16(v);
    hi[idx] = h;
    lo[idx] = __float2bfloat16(v - __bfloat162float(h));
}

// conv11 weight transpose: [co][ci][9] -> [(ci*9+t)*3 + co]
__global__ void transpose_w(const float* __restrict__ src, float* __restrict__ dst,
                            int Cin, int Cout)
{
    int idx = blockIdx.x * blockDim.x + threadIdx.x;
    int total = Cin * Cout * 9;
    if (idx >= total) return;
    int co = idx % Cout;
    int t  = (idx / Cout) % 9;
    int ci = idx / (Cout * 9);
    dst[idx] = src[((size_t)co * Cin + ci) * 9 + t];
}

// ======================= per-sample masked gaussian kernels ===============
__global__ void build_blur(const float* __restrict__ alphas)
{
    int i = threadIdx.x;
    if (i >= 12) return;
    float alpha = alphas[i];
    float k = floorf(floorf(alpha * 8.0f) * 0.5f) * 2.0f + 1.0f;
    float r = (k - 1.0f) * 0.5f;
    float vals[81];
    float sum = 0.0f;
    for (int y = 0; y < 9; y++)
        for (int x = 0; x < 9; x++) {
            float cy = (float)(y - 4), cx = (float)(x - 4);
            float g = expf(-(cy*cy + cx*cx) / 512.0f);
            float v = (fabsf(cy) <= r && fabsf(cx) <= r) ? g : 0.0f;
            vals[y*9 + x] = v;
            sum += v;
        }
    float inv = 1.0f / sum;
    for (int j = 0; j < 81; j++) g_blurk[i*81 + j] = vals[j] * inv;
}

// ======================= channel stats (mean + unbiased std) ==============
__global__ void stats_kernel(const float* __restrict__ x, int HW, int which)
{
    int bc = blockIdx.x;
    const float* p = x + (size_t)bc * HW;
    float s = 0.f, s2 = 0.f;
    for (int i = threadIdx.x; i < HW; i += blockDim.x) {
        float v = p[i];
        s += v;
        s2 = fmaf(v, v, s2);
    }
#pragma unroll
    for (int o = 16; o > 0; o >>= 1) {
        s  += __shfl_down_sync(0xffffffffu, s,  o);
        s2 += __shfl_down_sync(0xffffffffu, s2, o);
    }
    __shared__ float rs[8], rs2[8];
    int w = threadIdx.x >> 5, l = threadIdx.x & 31;
    if (l == 0) { rs[w] = s; rs2[w] = s2; }
    __syncthreads();
    if (threadIdx.x == 0) {
        float S = 0.f, S2 = 0.f;
        for (int i = 0; i < 8; i++) { S += rs[i]; S2 += rs2[i]; }
        float n = (float)HW;
        float mean = S / n;
        float var = (S2 - S * S / n) / (n - 1.0f);
        if (var < 0.f) var = 0.f;
        float sd = sqrtf(var);
        if (which == 0) { g_cm[bc] = mean; g_cs[bc]  = sd; }
        else            { g_sm[bc] = mean; g_ssd[bc] = sd; }
    }
}

__global__ void combine_kernel(int n)
{
    int i = blockIdx.x * blockDim.x + threadIdx.x;
    if (i >= n) return;
    float a = g_ssd[i] / (g_cs[i] + 1e-5f);
    g_a[i]   = a;
    g_bsh[i] = g_sm[i] - g_cm[i] * a;
}

__global__ void wct_apply_kernel(float* __restrict__ x, int sh)
{
    int idx = blockIdx.x * blockDim.x + threadIdx.x;
    int bc = idx >> sh;
    x[idx] = fmaf(x[idx], g_a[bc], g_bsh[bc]);
}

// hh = x - up2(avgpool2(x))
__global__ void hh_kernel(const float* __restrict__ x, float* __restrict__ o,
                          int wsh, int hsh)
{
    int idx = blockIdx.x * blockDim.x + threadIdx.x;
    int W = 1 << wsh;
    int xc = idx & (W - 1);
    int y  = (idx >> wsh) & ((1 << hsh) - 1);
    size_t chbase = ((size_t)(idx >> (wsh + hsh))) << (wsh + hsh);
    int y0 = y & ~1, x0 = xc & ~1;
    const float* ch = x + chbase;
    size_t b0 = (size_t)y0 * W + x0;
    float avg = 0.25f * (ch[b0] + ch[b0 + 1] + ch[b0 + W] + ch[b0 + W + 1]);
    o[idx] = x[idx] - avg;
}

// out = up2(small) + g_a[bc] * blur9x9(hh)   (replicate pad 4)
#define BT 16
__global__ void blur_add_kernel(const float* __restrict__ hh,
                                const float* __restrict__ small,
                                float* __restrict__ out,
                                int C, int H, int W, int lvl)
{
    int bc = blockIdx.z;
    int b  = bc / C;
    int ty0 = blockIdx.y * BT, tx0 = blockIdx.x * BT;
    __shared__ float tile[BT + 8][BT + 9];
    __shared__ float ker[81];
    int tid = threadIdx.x;
    if (tid < 81) ker[tid] = g_blurk[(b * 3 + lvl) * 81 + tid];
    const float* src = hh + (size_t)bc * H * W;
    for (int i = tid; i < (BT + 8) * (BT + 8); i += 256) {
        int r = i / (BT + 8), c = i % (BT + 8);
        int gy = ty0 - 4 + r; gy = gy < 0 ? 0 : (gy >= H ? H - 1 : gy);
        int gx = tx0 - 4 + c; gx = gx < 0 ? 0 : (gx >= W ? W - 1 : gx);
        tile[r][c] = src[(size_t)gy * W + gx];
    }
    __syncthreads();
    int ly = tid >> 4, lx = tid & 15;
    float s = 0.f;
#pragma unroll
    for (int dy = 0; dy < 9; dy++)
#pragma unroll
        for (int dx = 0; dx < 9; dx++)
            s = fmaf(ker[dy * 9 + dx], tile[ly + dy][lx + dx], s);
    int y = ty0 + ly, x = tx0 + lx;
    int W2 = W >> 1;
    size_t hw2 = (size_t)(H >> 1) * W2;
    float up = small[(size_t)bc * hw2 + (size_t)(y >> 1) * W2 + (x >> 1)];
    out[(size_t)bc * H * W + (size_t)y * W + x] = up + g_a[bc] * s;
}

// ======================= mma.sync conv3x3 =================================
// Block: 128 px (16x8) x 64 co, 256 threads, 8 warps (4 M x 2 N).
// Halo converted to bf16 hi/lo once per 64-ci chunk, stored [pos][ci64]
// (144 B stride). Per tap: ldmatrix at shifted pos + 24 mma per k16 step.
// B tiles double-buffered via cp.async: next tap prefetched during compute.
#define OFF_AHI 0
#define OFF_ALO 25920
#define OFF_B   51840      /* 2 buffers x (hi 9216 + lo 9216) */
#define SMEM_SZ 88704

__global__ __launch_bounds__(256, 2)
void conv_mma_kernel(const float* __restrict__ in,
                     const __nv_bfloat16* __restrict__ wHi,
                     const __nv_bfloat16* __restrict__ wLo,
                     const float* __restrict__ bias,
                     float* __restrict__ out,
                     int Cin, int Cout, int H, int W, int doRelu)
{
    extern __shared__ __align__(16) char smem[];
    const uint32_t sb = smem_u32(smem);
    __nv_bfloat16* haloHi = (__nv_bfloat16*)(smem + OFF_AHI);
    __nv_bfloat16* haloLo = (__nv_bfloat16*)(smem + OFF_ALO);

    const int tid  = threadIdx.x;
    const int lane = tid & 31;
    const int wid  = tid >> 5;
    const int warp_m = wid & 3;     // px group (32 px)
    const int warp_n = wid >> 2;    // co group (32 co)

    const int cog     = Cout >> 6;
    const int b       = blockIdx.z / cog;
    const int co_base = (blockIdx.z % cog) << 6;
    const int x0 = blockIdx.x * 16;
    const int y0 = blockIdx.y * 8;
    const size_t chsz = (size_t)H * W;
    const float* inB = in + (size_t)b * Cin * chsz;
    const int nch = Cin >> 6;
    const int nit = nch * 9;

    float acc[2][4][4];
#pragma unroll
    for (int mi = 0; mi < 2; mi++)
#pragma unroll
        for (int ni = 0; ni < 4; ni++)
#pragma unroll
            for (int q = 0; q < 4; q++) acc[mi][ni][q] = 0.f;

    // per-thread ldmatrix addressing constants
    const int aR = lane & 15, aK = lane >> 4;             // A: row px, k-half
    const int bN = (((lane >> 4) & 1) << 3) | (lane & 7); // B: n row
    const int bK = (lane >> 3) & 1;                       // B: k-half

    // ---- B prefetch: tile for iteration itv -> buffer itv&1 ----
    auto issueB = [&](int itv) {
        int chv = itv / 9, tapv = itv - 9 * chv;
        const uint4* gHi = (const uint4*)
            (wHi + ((size_t)(tapv * nch + chv) * Cout + co_base) * 64);
        const uint4* gLo = (const uint4*)
            (wLo + ((size_t)(tapv * nch + chv) * Cout + co_base) * 64);
        uint32_t dst = sb + OFF_B + (uint32_t)(itv & 1) * 18432;
        for (int i = tid; i < 512; i += 256) {
            int co = i >> 3, g = i & 7;
            uint32_t ad = (uint32_t)(co * 144 + g * 16);
            CP_ASYNC16(dst + ad,        gHi + i);
            CP_ASYNC16(dst + 9216 + ad, gLo + i);
        }
        CP_COMMIT();
    };

    issueB(0);
    int it = 0;
    for (int ch = 0; ch < nch; ch++) {
        __syncthreads();   // previous chunk's compute done before halo overwrite
        // ---- halo fill: fp32 gmem (reflect pad) -> bf16 hi/lo [pos][ci] ----
        for (int idx = tid; idx < 64 * 180; idx += 256) {
            int ci  = idx / 180;
            int pos = idx - ci * 180;
            int r = pos / 18, c = pos - r * 18;
            int gy = y0 - 1 + r; gy = gy < 0 ? -gy : (gy >= H ? 2*H - 2 - gy : gy);
            int gx = x0 - 1 + c; gx = gx < 0 ? -gx : (gx >= W ? 2*W - 2 - gx : gx);
            float v = inB[(size_t)(ch * 64 + ci) * chsz + (size_t)gy * W + gx];
            __nv_bfloat16 h = __float2bfloat16(v);
            haloHi[pos * 72 + ci] = h;
            haloLo[pos * 72 + ci] = __float2bfloat16(v - __bfloat162float(h));
        }

        for (int tap = 0; tap < 9; tap++) {
            CP_WAIT0();        // B buffer (it&1) landed
            __syncthreads();   // visible to all; prior tap compute finished
            if (it + 1 < nit) issueB(it + 1);

            // ---- compute from buffer it&1 ----
            const int dy = tap / 3, dx = tap - 3 * dy;
            const uint32_t aBase = sb + OFF_AHI +
                (uint32_t)(((2*warp_m + dy) * 18 + aR + dx) * 144 + aK * 16);
            const uint32_t bBase = sb + OFF_B + (uint32_t)(it & 1) * 18432 +
                (uint32_t)((warp_n * 32 + bN) * 144 + bK * 16);

#pragma unroll
            for (int ks = 0; ks < 4; ks++) {
                const uint32_t ko = ks * 32;
                uint32_t ahi[2][4], alo[2][4], bhi[4], blo[4], bhi2[4], blo2[4];
                ldsm4(ahi[0], aBase + ko);
                ldsm4(ahi[1], aBase + ko + 18*144);
                ldsm4(alo[0], aBase + ko + (OFF_ALO - OFF_AHI));
                ldsm4(alo[1], aBase + ko + (OFF_ALO - OFF_AHI) + 18*144);
                ldsm4(bhi,  bBase + ko);
                ldsm4(bhi2, bBase + ko + 16*144);
                ldsm4(blo,  bBase + ko + 9216);
                ldsm4(blo2, bBase + ko + 9216 + 16*144);
#pragma unroll
                for (int mi = 0; mi < 2; mi++) {
                    mma16816(acc[mi][0], ahi[mi], bhi);
                    mma16816(acc[mi][1], ahi[mi], bhi + 2);
                    mma16816(acc[mi][2], ahi[mi], bhi2);
                    mma16816(acc[mi][3], ahi[mi], bhi2 + 2);
                    mma16816(acc[mi][0], ahi[mi], blo);
                    mma16816(acc[mi][1], ahi[mi], blo + 2);
                    mma16816(acc[mi][2], ahi[mi], blo2);
                    mma16816(acc[mi][3], ahi[mi], blo2 + 2);
                    mma16816(acc[mi][0], alo[mi], bhi);
                    mma16816(acc[mi][1], alo[mi], bhi + 2);
                    mma16816(acc[mi][2], alo[mi], bhi2);
                    mma16816(acc[mi][3], alo[mi], bhi2 + 2);
                }
            }
            it++;
        }
    }

    // ---- epilogue: bias + relu + store ----
    const int xr = lane >> 2;
    const int c0 = (lane & 3) << 1;
#pragma unroll
    for (int ni = 0; ni < 4; ni++) {
        int co = co_base + warp_n * 32 + ni * 8 + c0;
        float bv0 = __ldg(&bias[co]);
        float bv1 = __ldg(&bias[co + 1]);
        float* o0 = out + ((size_t)b * Cout + co) * chsz;
        float* o1 = o0 + chsz;
#pragma unroll
        for (int mi = 0; mi < 2; mi++) {
            int yy = y0 + 2 * warp_m + mi;
            size_t rb = (size_t)yy * W + x0;
            float v0 = acc[mi][ni][0] + bv0;
            float v1 = acc[mi][ni][1] + bv1;
            float v2 = acc[mi][ni][2] + bv0;
            float v3 = acc[mi][ni][3] + bv1;
            if (doRelu) {
                v0 = fmaxf(v0, 0.f); v1 = fmaxf(v1, 0.f);
                v2 = fmaxf(v2, 0.f); v3 = fmaxf(v3, 0.f);
            }
            o0[rb + xr]     = v0;
            o1[rb + xr]     = v1;
            o0[rb + xr + 8] = v2;
            o1[rb + xr + 8] = v3;
        }
    }
}

// ======================= final conv (Cin=64, Cout=3, no relu) =============
__global__ __launch_bounds__(256)
void conv11_kernel(const float* __restrict__ in, const float* __restrict__ wT,
                   const float* __restrict__ bias, float* __restrict__ out,
                   int H, int W)
{
    int b = blockIdx.z;
    int ty0 = blockIdx.y * 16, tx0 = blockIdx.x * 16;
    __shared__ float sIn[8][18][18];
    __shared__ float sW[64 * 9 * 3];
    int tid = threadIdx.x;
    for (int i = tid; i < 64 * 9 * 3; i += 256) sW[i] = wT[i];
    float a0 = 0.f, a1 = 0.f, a2 = 0.f;
    int ly = tid >> 4, lx = tid & 15;
    const size_t chsz = (size_t)H * W;
    const float* inB = in + (size_t)b * 64 * chsz;
    for (int c0 = 0; c0 < 64; c0 += 8) {
        __syncthreads();
        for (int i = tid; i < 8 * 324; i += 256) {
            int ci = i / 324; int rem = i - ci * 324;
            int r = rem / 18, c = rem - r * 18;
            int gy = ty0 - 1 + r; gy = gy < 0 ? -gy : (gy >= H ? 2*H - 2 - gy : gy);
            int gx = tx0 - 1 + c; gx = gx < 0 ? -gx : (gx >= W ? 2*W - 2 - gx : gx);
            sIn[ci][r][c] = inB[(size_t)(c0 + ci) * chsz + (size_t)gy * W + gx];
        }
        __syncthreads();
        for (int ci = 0; ci < 8; ci++) {
#pragma unroll
            for (int t = 0; t < 9; t++) {
                float v = sIn[ci][ly + t / 3][lx + t % 3];
                int wb = ((c0 + ci) * 9 + t) * 3;
                a0 = fmaf(v, sW[wb + 0], a0);
                a1 = fmaf(v, sW[wb + 1], a1);
                a2 = fmaf(v, sW[wb + 2], a2);
            }
        }
    }
    int y = ty0 + ly, x = tx0 + lx;
    size_t off = (size_t)y * W + x;
    out[((size_t)b * 3 + 0) * chsz + off] = a0 + bias[0];
    out[((size_t)b * 3 + 1) * chsz + off] = a1 + bias[1];
    out[((size_t)b * 3 + 2) * chsz + off] = a2 + bias[2];
}

// ======================= host launcher ====================================
extern "C" void kernel_launch(void* const* d_in, const int* in_sizes, int n_in,
                              void* d_out, int out_size)
{
    const float* x   = (const float*)d_in[0];
    const float* c34 = (const float*)d_in[1];
    const float* c22 = (const float*)d_in[2];
    const float* c12 = (const float*)d_in[3];
    const float* s34 = (const float*)d_in[4];
    const float* s31 = (const float*)d_in[5];
    const float* s22 = (const float*)d_in[6];
    const float* s21 = (const float*)d_in[7];
    const float* s12 = (const float*)d_in[8];
    const float* s11 = (const float*)d_in[9];
    const float* alphas = (const float*)d_in[10];
    const float* wsrc[9] = { (const float*)d_in[11], (const float*)d_in[13],
                             (const float*)d_in[15], (const float*)d_in[17],
                             (const float*)d_in[19], (const float*)d_in[21],
                             (const float*)d_in[23], (const float*)d_in[25],
                             (const float*)d_in[27] };
    const float* bsrc[9] = { (const float*)d_in[12], (const float*)d_in[14],
                             (const float*)d_in[16], (const float*)d_in[18],
                             (const float*)d_in[20], (const float*)d_in[22],
                             (const float*)d_in[24], (const float*)d_in[26],
                             (const float*)d_in[28] };
    float* outp = (float*)d_out;

    float *pA, *pB, *pC, *wT;
    __nv_bfloat16 *wHi, *wLo;
    cudaGetSymbolAddress((void**)&pA, g_bufA);
    cudaGetSymbolAddress((void**)&pB, g_bufB);
    cudaGetSymbolAddress((void**)&pC, g_bufC);
    cudaGetSymbolAddress((void**)&wT, g_wT);
    cudaGetSymbolAddress((void**)&wHi, g_wHi);
    cudaGetSymbolAddress((void**)&wLo, g_wLo);

    cudaFuncSetAttribute(conv_mma_kernel,
                         cudaFuncAttributeMaxDynamicSharedMemorySize, SMEM_SZ);

    const int cins[8]  = {512,256,256,256,256,128,128,64};
    const int couts[8] = {256,256,256,256,128,128, 64,64};
    size_t offs[8]; size_t off = 0;
    for (int l = 0; l < 8; l++) { offs[l] = off; off += (size_t)cins[l]*couts[l]*9; }

    auto conv = [&](const float* in, int l, const float* bias, float* out,
                    int H, int W) {
        int Cin = cins[l], Cout = couts[l];
        dim3 g(W/16, H/8, 4 * (Cout/64));
        conv_mma_kernel<<<g, 256, SMEM_SZ>>>(in, wHi + offs[l], wLo + offs[l],
                                             bias, out, Cin, Cout, H, W, 1);
    };

    // Launch order arranged so launch #6 (ncu -s 5 -c 1 target) is conv layer 0.
    prep_w<<<(cins[0]*couts[0]*9 + 255)/256, 256>>>(wsrc[0], wHi + offs[0],
                                                    wLo + offs[0], cins[0], couts[0]); // 1
    transpose_w<<<(64*3*9 + 255)/256, 256>>>(wsrc[8], wT, 64, 3);                      // 2
    build_blur<<<1, 32>>>(alphas);                                                     // 3
    stats_kernel<<<1024, 256>>>(c34, 64*64, 0);                                        // 4
    stats_kernel<<<1024, 256>>>(s34, 64*64, 1);                                        // 5
    conv(x, 0, bsrc[0], pA, 32, 32);                                                   // 6
    for (int l = 1; l < 8; l++) {
        int total = cins[l]*couts[l]*9;
        prep_w<<<(total + 255)/256, 256>>>(wsrc[l], wHi + offs[l], wLo + offs[l],
                                           cins[l], couts[l]);
    }

    // ---- level 4 -> 3 ----
    combine_kernel<<<4, 256>>>(1024);
    hh_kernel<<<(4*256*64*64)/256, 256>>>(c34, pC, 6, 6);
    blur_add_kernel<<<dim3(4,4,1024), 256>>>(pC, pA, pB, 256, 64, 64, 2);
    conv(pB, 1, bsrc[1], pA, 64, 64);
    conv(pA, 2, bsrc[2], pB, 64, 64);
    conv(pB, 3, bsrc[3], pA, 64, 64);
    stats_kernel<<<1024, 256>>>(pA,  64*64, 0);
    stats_kernel<<<1024, 256>>>(s31, 64*64, 1);
    combine_kernel<<<4, 256>>>(1024);
    wct_apply_kernel<<<(4*256*64*64)/256, 256>>>(pA, 12);
    conv(pA, 4, bsrc[4], pB, 64, 64);

    // ---- level 3 -> 2 ----
    stats_kernel<<<512, 256>>>(c22, 128*128, 0);
    stats_kernel<<<512, 256>>>(s22, 128*128, 1);
    combine_kernel<<<2, 256>>>(512);
    hh_kernel<<<(4*128*128*128)/256, 256>>>(c22, pC, 7, 7);
    blur_add_kernel<<<dim3(8,8,512), 256>>>(pC, pB, pA, 128, 128, 128, 1);
    conv(pA, 5, bsrc[5], pB, 128, 128);
    stats_kernel<<<512, 256>>>(pB,  128*128, 0);
    stats_kernel<<<512, 256>>>(s21, 128*128, 1);
    combine_kernel<<<2, 256>>>(512);
    wct_apply_kernel<<<(4*128*128*128)/256, 256>>>(pB, 14);
    conv(pB, 6, bsrc[6], pA, 128, 128);

    // ---- level 2 -> 1 ----
    stats_kernel<<<256, 256>>>(c12, 256*256, 0);
    stats_kernel<<<256, 256>>>(s12, 256*256, 1);
    combine_kernel<<<1, 256>>>(256);
    hh_kernel<<<(4*64*256*256)/256, 256>>>(c12, pC, 8, 8);
    blur_add_kernel<<<dim3(16,16,256), 256>>>(pC, pA, pB, 64, 256, 256, 0);
    conv(pB, 7, bsrc[7], pA, 256, 256);
    stats_kernel<<<256, 256>>>(pA,  256*256, 0);
    stats_kernel<<<256, 256>>>(s11, 256*256, 1);
    combine_kernel<<<1, 256>>>(256);
    wct_apply_kernel<<<(4*64*256*256)/256, 256>>>(pA, 16);
    conv11_kernel<<<dim3(16,16,4), 256>>>(pA, wT, bsrc[8], outp, 256, 256);
}